// round 11
// baseline (speedup 1.0000x reference)
#include <cuda_runtime.h>
#include <math.h>

#define IMG 256
#define MAX_R 64
#define N_AG 2047
#define N_OB 2048
#define N_ENT 4095
#define FOVH 0.7853981633974483f   /* pi/4 = FOV/2 */
#define ONEBITS 0x3F800000u        /* __float_as_uint(1.0f) */

#define SPLIT 2                    /* warps per entity (even/odd rows) */
#define TPB 256                    /* 8 warps per block */
#define NWARP (4096 * SPLIT)
#define NBLK (NWARP / (TPB / 32))  /* 1024 blocks */

__global__ void init_kernel(uint4* __restrict__ outb) {
    int i = blockIdx.x * blockDim.x + threadIdx.x;   /* 16384 uint4 */
    outb[i] = make_uint4(ONEBITS, ONEBITS, ONEBITS, ONEBITS);
}

__global__ __launch_bounds__(TPB)
void splat_kernel(const float* __restrict__ agent,
                  const float* __restrict__ goal,
                  const float* __restrict__ others,
                  const float* __restrict__ obs,
                  unsigned int* __restrict__ outb) {
    int wg   = (blockIdx.x * TPB + threadIdx.x) >> 5;   /* global warp id */
    int e    = wg >> 1;                                  /* entity */
    int par  = wg & 1;                                   /* row parity */
    unsigned lane = threadIdx.x & 31;
    if (e >= N_ENT) return;

    /* camera basis (uniform across warp) */
    float ax = agent[0], ay = agent[1];
    float vx = goal[0] - ax, vy = goal[1] - ay;
    float inv = 1.0f / (sqrtf(vx * vx + vy * vy) + 1e-8f);
    vx *= inv; vy *= inv;
    float c = vy, s = vx;

    float ex, ey, r, h;
    if (e < N_AG) {
        ex = others[2 * e];
        ey = others[2 * e + 1];
        r  = 0.05f;
        h  = 0.2f;
    } else {
        int o = e - N_AG;
        ex = obs[3 * o];
        ey = obs[3 * o + 1];
        r  = obs[3 * o + 2];
        h  = 0.5f;
    }

    float rx = ex - ax, ry = ey - ay;
    float camx =  c * rx + s * ry;
    float camy = -s * rx + c * ry;
    float dist = sqrtf(camx * camx + camy * camy);
    float angle = atan2f(camx, camy);

    if (!((camy >= 0.0f) && (dist <= 3.0f) && (fabsf(angle) <= FOVH)))
        return;

    float pixel_x = angle / FOVH * 0.5f;
    int pxi = (int)floorf((pixel_x + 0.5f) * (float)IMG);
    int pr  = (int)floorf(r / (dist + 1e-8f) * (float)IMG * 0.5f);
    pr = min(max(pr, 1), MAX_R);
    if (pxi + pr < 0 || pxi - pr >= IMG) return;

    float depth = fminf(dist / 3.0f, 1.0f) * (1.0f - h * 0.3f);
    depth = fmaxf(depth, 0.0f);
    unsigned dbits = __float_as_uint(depth);
    int pr2 = pr * pr;

    /* paint rows dy = -pr+par, -pr+par+2, ... ; py = 128+dy always in-bounds */
    for (int dy = -pr + par; dy <= pr; dy += SPLIT) {
        int t = pr2 - dy * dy;                   /* >= 0 */
        int w = (int)sqrtf((float)t);            /* exact floor for t <= 4096 */
        int x0   = pxi - w;
        int span = 2 * w + 1;
        int rowbase = (IMG / 2 + dy) * IMG;
        for (int i = (int)lane; i < span; i += 32) {
            int px = x0 + i;
            if ((unsigned)px < IMG)
                atomicMin(&outb[rowbase + px], dbits);   /* RED.E.MIN */
        }
    }
}

extern "C" void kernel_launch(void* const* d_in, const int* in_sizes, int n_in,
                              void* d_out, int out_size) {
    const float* agent  = (const float*)d_in[0];
    const float* goal   = (const float*)d_in[1];
    const float* others = (const float*)d_in[2];
    const float* obs    = (const float*)d_in[3];
    unsigned int* outb  = (unsigned int*)d_out;

    init_kernel<<<(IMG * IMG / 4) / 256, 256>>>((uint4*)outb);
    splat_kernel<<<NBLK, TPB>>>(agent, goal, others, obs, outb);
}

// round 12
// speedup vs baseline: 2.0835x; 2.0835x over previous
#include <cuda_runtime.h>
#include <math.h>

#define IMG 256
#define MAX_R 64
#define N_AG 2047
#define N_OB 2048
#define N_ENT 4095
#define FOVH 0.7853981633974483f   /* pi/4 = FOV/2 */

#define TILE 16
#define BAND_LO 64                 /* first reachable row (128-64) */
#define NTC (IMG / TILE)           /* 16 tile cols */
#define NTR 9                      /* 9 tile rows: rows 64..207 (>=193 unreachable) */
#define NPB (NTC * NTR)            /* 144 paint blocks, single wave */

/* dense valid records: {pxi<<16 | pr*pr, depth_bits} */
__device__ uint2 g_rec[4096];
__device__ int   g_nvalid = 0;     /* self-reset by paint each run */
__device__ int   g_done   = 0;

__global__ void transform_kernel(const float* __restrict__ agent,
                                 const float* __restrict__ goal,
                                 const float* __restrict__ others,
                                 const float* __restrict__ obs) {
    int e = blockIdx.x * blockDim.x + threadIdx.x;
    unsigned lane = threadIdx.x & 31;

    float ax = agent[0], ay = agent[1];
    float vx = goal[0] - ax, vy = goal[1] - ay;
    float inv = 1.0f / (sqrtf(vx * vx + vy * vy) + 1e-8f);
    vx *= inv; vy *= inv;
    float c = vy, s = vx;

    bool valid = false;
    uint2 rec = make_uint2(0u, 0u);

    if (e < N_ENT) {
        float ex, ey, r, h;
        if (e < N_AG) {
            ex = others[2 * e];
            ey = others[2 * e + 1];
            r  = 0.05f;
            h  = 0.2f;
        } else {
            int o = e - N_AG;
            ex = obs[3 * o];
            ey = obs[3 * o + 1];
            r  = obs[3 * o + 2];
            h  = 0.5f;
        }
        float rx = ex - ax, ry = ey - ay;
        float camx =  c * rx + s * ry;
        float camy = -s * rx + c * ry;
        float dist = sqrtf(camx * camx + camy * camy);
        float angle = atan2f(camx, camy);

        if ((camy >= 0.0f) && (dist <= 3.0f) && (fabsf(angle) <= FOVH)) {
            float pixel_x = angle / FOVH * 0.5f;
            int pxi = (int)floorf((pixel_x + 0.5f) * (float)IMG);
            int pr  = (int)floorf(r / (dist + 1e-8f) * (float)IMG * 0.5f);
            pr = min(max(pr, 1), MAX_R);
            if (pxi + pr >= 0 && pxi - pr < IMG) {      /* touches image */
                float depth = fminf(dist / 3.0f, 1.0f) * (1.0f - h * 0.3f);
                depth = fmaxf(depth, 0.0f);
                rec.x = ((unsigned)pxi << 16) | (unsigned)(pr * pr);
                rec.y = __float_as_uint(depth);
                valid = true;
            }
        }
    }

    unsigned m = __ballot_sync(0xffffffffu, valid);
    if (valid) {
        int leader = __ffs(m) - 1;
        int base = 0;
        if ((int)lane == leader) base = atomicAdd(&g_nvalid, __popc(m));
        base = __shfl_sync(m, base, leader);
        g_rec[base + __popc(m & ((1u << lane) - 1))] = rec;
    }
}

__global__ __launch_bounds__(256)
void paint_kernel(float* __restrict__ out) {
    __shared__ uint2 s_rec[4096];      /* tile-local: {pxi<<16|pr2, depth} */
    __shared__ int   s_cnt;
    __shared__ int   s_n;

    int tid = threadIdx.x;
    unsigned lane = tid & 31;
    int tc   = blockIdx.x & (NTC - 1);         /* tile col */
    int band = blockIdx.x >> 4;                /* tile row */
    int c_lo = tc * TILE, c_hi = c_lo + TILE - 1;
    int r_lo = BAND_LO + band * TILE, r_hi = r_lo + TILE - 1;

    if (tid == 0) { s_n = g_nvalid; s_cnt = 0; }

    /* background rows (0..63 and 193..255): plain 1.0 stores, disjoint from
       all tiles; each block covers a slice of the 32512-pixel background. */
    {
        int idx = blockIdx.x * 256 + tid;              /* < 36864 */
        if (idx < 16384) {
            out[idx] = 1.0f;                           /* rows 0..63 */
        } else {
            int j = idx - 16384;
            if (j < 16128) out[(193 * IMG) + j] = 1.0f; /* rows 193..255 */
        }
    }
    __syncthreads();
    int n = s_n;

    /* self-reset for next replay (proven pattern): every block captured n
       into smem before the last arriver resets. */
    if (tid == 0) {
        int d = atomicAdd(&g_done, 1);
        if (d == NPB - 1) { g_nvalid = 0; g_done = 0; }
    }

    /* Phase A: exact disk-vs-tile test, warp-aggregated smem compaction */
    for (int e0 = 0; e0 < n; e0 += 256) {
        int e = e0 + tid;
        bool hit = false;
        uint2 g = make_uint2(0u, 0u);
        if (e < n) {
            g = __ldg(&g_rec[e]);
            int pxi = (int)g.x >> 16;
            int pr2 = (int)(g.x & 0xffffu);
            int cx  = min(max(pxi, c_lo), c_hi);       /* nearest tile col */
            int cy  = min(max(IMG / 2, r_lo), r_hi);   /* nearest tile row */
            int dxm = pxi - cx;
            int dym = IMG / 2 - cy;
            hit = (dxm * dxm + dym * dym <= pr2);
        }
        unsigned m = __ballot_sync(0xffffffffu, hit);
        if (hit) {
            int leader = __ffs(m) - 1;
            int base = 0;
            if ((int)lane == leader) base = atomicAdd(&s_cnt, __popc(m));
            base = __shfl_sync(m, base, leader);
            s_rec[base + __popc(m & ((1u << lane) - 1))] = g;
        }
    }
    __syncthreads();
    int nc = s_cnt;

    /* Phase B: one pixel per thread */
    int px = c_lo + (tid & (TILE - 1));
    int py = r_lo + (tid >> 4);
    int dy = py - IMG / 2;
    int d2 = dy * dy;
    float mv = 1.0f;

    for (int e = 0; e < nc; e++) {
        uint2 rr = s_rec[e];                            /* broadcast LDS.64 */
        int pxi = (int)rr.x >> 16;
        int pr2 = (int)(rr.x & 0xffffu);
        int dx  = px - pxi;
        if (dx * dx + d2 <= pr2) mv = fminf(mv, __uint_as_float(rr.y));
    }
    out[py * IMG + px] = mv;
}

extern "C" void kernel_launch(void* const* d_in, const int* in_sizes, int n_in,
                              void* d_out, int out_size) {
    const float* agent  = (const float*)d_in[0];
    const float* goal   = (const float*)d_in[1];
    const float* others = (const float*)d_in[2];
    const float* obs    = (const float*)d_in[3];
    float* out          = (float*)d_out;

    transform_kernel<<<32, 128>>>(agent, goal, others, obs);
    paint_kernel<<<NPB, 256>>>(out);
}

// round 13
// speedup vs baseline: 2.5238x; 1.2113x over previous
#include <cuda_runtime.h>
#include <math.h>

#define IMG 256
#define MAX_R 64
#define N_AG 2047
#define N_OB 2048
#define N_ENT 4095
#define FOVH 0.7853981633974483f   /* pi/4 = FOV/2 */
#define PT 1024
#define NB (IMG / 2)               /* 128 blocks, 2 columns each: single wave */

__global__ __launch_bounds__(PT)
void render_kernel(const float* __restrict__ agent,
                   const float* __restrict__ goal,
                   const float* __restrict__ others,
                   const float* __restrict__ obs,
                   float* __restrict__ out) {
    __shared__ uint2 s_rec[4096];      /* stripe list: {pxi<<16|pr2, depth} */
    __shared__ int   s_wcnt[32];
    __shared__ int   s_wbase[33];

    int tid  = threadIdx.x;
    int warp = tid >> 5;
    unsigned lane = tid & 31;
    int c0 = blockIdx.x * 2;
    int c1 = c0 + 1;

    /* camera basis */
    float ax = agent[0], ay = agent[1];
    float vx = goal[0] - ax, vy = goal[1] - ay;
    float inv = 1.0f / (sqrtf(vx * vx + vy * vy) + 1e-8f);
    vx *= inv; vy *= inv;
    float cb = vy, sb = vx;

    /* ---- stage all entity data first (batched, high MLP) ---- */
    float ex[4], ey[4], er[4], eh[4];
    #pragma unroll
    for (int k = 0; k < 4; k++) {
        int e = tid + k * PT;
        if (e < N_AG) {
            const float2 p = __ldg((const float2*)(others + 2 * e));
            ex[k] = p.x; ey[k] = p.y; er[k] = 0.05f; eh[k] = 0.2f;
        } else if (e < N_ENT) {
            int o = e - N_AG;
            ex[k] = __ldg(obs + 3 * o);
            ey[k] = __ldg(obs + 3 * o + 1);
            er[k] = __ldg(obs + 3 * o + 2);
            eh[k] = 0.5f;
        } else {
            ex[k] = 1e9f; ey[k] = -1e9f; er[k] = 0.0f; eh[k] = 0.0f;
        }
    }

    /* ---- transform + stripe hit test + ballot ---- */
    unsigned recx[4], recy[4], msk[4];
    int cnt = 0;
    #pragma unroll
    for (int k = 0; k < 4; k++) {
        float rx = ex[k] - ax, ry = ey[k] - ay;
        float camx =  cb * rx + sb * ry;
        float camy = -sb * rx + cb * ry;
        float dist = sqrtf(camx * camx + camy * camy);
        float angle = atan2f(camx, camy);

        bool hit = false;
        recx[k] = 0u; recy[k] = 0u;
        if ((camy >= 0.0f) && (dist <= 3.0f) && (fabsf(angle) <= FOVH)) {
            float pixel_x = angle / FOVH * 0.5f;
            int pxi = (int)floorf((pixel_x + 0.5f) * (float)IMG);
            int pr  = (int)floorf(er[k] / (dist + 1e-8f) * (float)IMG * 0.5f);
            pr = min(max(pr, 1), MAX_R);
            int pr2 = pr * pr;
            int cxn = min(max(pxi, c0), c1);
            int dxm = pxi - cxn;
            if (dxm * dxm <= pr2) {
                float depth = fminf(dist / 3.0f, 1.0f) * (1.0f - eh[k] * 0.3f);
                depth = fmaxf(depth, 0.0f);
                recx[k] = ((unsigned)pxi << 16) | (unsigned)pr2;
                recy[k] = __float_as_uint(depth);
                hit = true;
            }
        }
        msk[k] = __ballot_sync(0xffffffffu, hit);
        cnt   += __popc(msk[k]);
    }
    if (lane == 0) s_wcnt[warp] = cnt;
    __syncthreads();

    if (warp == 0) {                    /* exclusive scan of 32 warp counts */
        int v = s_wcnt[lane];
        int incl = v;
        #pragma unroll
        for (int off = 1; off < 32; off <<= 1) {
            int t = __shfl_up_sync(0xffffffffu, incl, off);
            if ((int)lane >= off) incl += t;
        }
        s_wbase[lane] = incl - v;
        if (lane == 31) s_wbase[32] = incl;
    }
    __syncthreads();

    int base = s_wbase[warp];
    unsigned pre = (1u << lane) - 1u;
    #pragma unroll
    for (int k = 0; k < 4; k++) {
        if (recy[k] != 0u || (msk[k] >> lane) & 1u) {   /* hit iff bit set */
            if ((msk[k] >> lane) & 1u)
                s_rec[base + __popc(msk[k] & pre)] = make_uint2(recx[k], recy[k]);
        }
        base += __popc(msk[k]);
    }
    __syncthreads();
    int nc = s_wbase[32];

    /* ---- phase B: half=tid&1, col=(tid>>1)&1, row=tid>>2 ---- */
    int half = tid & 1;
    int px   = c0 + ((tid >> 1) & 1);
    int row  = tid >> 2;
    int dy = row - IMG / 2;
    int d2 = dy * dy;
    float mv = 1.0f;

    if (d2 <= MAX_R * MAX_R) {
        for (int e = half; e < nc; e += 2) {
            uint2 rr = s_rec[e];
            int pxi = (int)(rr.x >> 16);
            int pr2 = (int)(rr.x & 0xffffu);
            int dx  = px - pxi;
            if (dx * dx + d2 <= pr2) mv = fminf(mv, __uint_as_float(rr.y));
        }
    }
    float other = __shfl_xor_sync(0xffffffffu, mv, 1);
    mv = fminf(mv, other);
    if (half == 0)
        out[row * IMG + px] = mv;
}

extern "C" void kernel_launch(void* const* d_in, const int* in_sizes, int n_in,
                              void* d_out, int out_size) {
    const float* agent  = (const float*)d_in[0];
    const float* goal   = (const float*)d_in[1];
    const float* others = (const float*)d_in[2];
    const float* obs    = (const float*)d_in[3];
    float* out          = (float*)d_out;

    render_kernel<<<NB, PT>>>(agent, goal, others, obs, out);
}

// round 14
// speedup vs baseline: 2.5313x; 1.0030x over previous
#include <cuda_runtime.h>
#include <math.h>

#define IMG 256
#define MAX_R 64
#define N_AG 2047
#define N_ENT 4095
#define FOVH 0.7853981633974483f   /* pi/4 = FOV/2 */
#define PT 1024
#define NB (IMG / 2)               /* 128 blocks, 2 columns each: single wave */

__global__ __launch_bounds__(PT)
void render_kernel(const float* __restrict__ agent,
                   const float* __restrict__ goal,
                   const float* __restrict__ others,
                   const float* __restrict__ obs,
                   float* __restrict__ out) {
    __shared__ uint2 s_rec0[4096];     /* col c0 list: {rem = pr2-dx2, depth} */
    __shared__ uint2 s_rec1[4096];     /* col c1 list */
    __shared__ int   s_wcnt[32];
    __shared__ int   s_wbase[33];      /* packed cnt0<<16 | cnt1 */

    int tid  = threadIdx.x;
    int warp = tid >> 5;
    unsigned lane = tid & 31;
    int c0 = blockIdx.x * 2;

    /* camera basis */
    float ax = agent[0], ay = agent[1];
    float vx = goal[0] - ax, vy = goal[1] - ay;
    float inv = 1.0f / (sqrtf(vx * vx + vy * vy) + 1e-8f);
    vx *= inv; vy *= inv;
    float cb = vy, sb = vx;

    /* stage entity data (batched, high MLP) */
    float ex[4], ey[4], er[4], eh[4];
    #pragma unroll
    for (int k = 0; k < 4; k++) {
        int e = tid + k * PT;
        if (e < N_AG) {
            float2 p = __ldg((const float2*)(others + 2 * e));
            ex[k] = p.x; ey[k] = p.y; er[k] = 0.05f; eh[k] = 0.2f;
        } else if (e < N_ENT) {
            int o = e - N_AG;
            ex[k] = __ldg(obs + 3 * o);
            ey[k] = __ldg(obs + 3 * o + 1);
            er[k] = __ldg(obs + 3 * o + 2);
            eh[k] = 0.5f;
        } else {
            ex[k] = 1e9f; ey[k] = -1e9f; er[k] = 0.0f; eh[k] = 0.0f;
        }
    }

    /* transform + per-column hit test + ballots */
    int rem0[4], rem1[4]; unsigned dep[4], m0[4], m1[4];
    int cnt0 = 0, cnt1 = 0;
    #pragma unroll
    for (int k = 0; k < 4; k++) {
        float rx = ex[k] - ax, ry = ey[k] - ay;
        float camx =  cb * rx + sb * ry;
        float camy = -sb * rx + cb * ry;
        float dist = sqrtf(camx * camx + camy * camy);
        float angle = atan2f(camx, camy);

        rem0[k] = -1; rem1[k] = -1; dep[k] = 0u;
        if ((camy >= 0.0f) && (dist <= 3.0f) && (fabsf(angle) <= FOVH)) {
            float pixel_x = angle / FOVH * 0.5f;
            int pxi = (int)floorf((pixel_x + 0.5f) * (float)IMG);
            int pr  = (int)floorf(er[k] / (dist + 1e-8f) * (float)IMG * 0.5f);
            pr = min(max(pr, 1), MAX_R);
            int pr2 = pr * pr;
            float depth = fminf(dist / 3.0f, 1.0f) * (1.0f - eh[k] * 0.3f);
            depth = fmaxf(depth, 0.0f);
            int dx0 = c0 - pxi;
            int dx1 = dx0 + 1;
            rem0[k] = pr2 - dx0 * dx0;
            rem1[k] = pr2 - dx1 * dx1;
            dep[k]  = __float_as_uint(depth);
        }
        m0[k] = __ballot_sync(0xffffffffu, rem0[k] >= 0);
        m1[k] = __ballot_sync(0xffffffffu, rem1[k] >= 0);
        cnt0 += __popc(m0[k]);
        cnt1 += __popc(m1[k]);
    }
    if (lane == 0) s_wcnt[warp] = (cnt0 << 16) | cnt1;
    __syncthreads();

    if (warp == 0) {                    /* packed exclusive scan (no carry) */
        int v = s_wcnt[lane];
        int incl = v;
        #pragma unroll
        for (int off = 1; off < 32; off <<= 1) {
            int t = __shfl_up_sync(0xffffffffu, incl, off);
            if ((int)lane >= off) incl += t;
        }
        s_wbase[lane] = incl - v;
        if (lane == 31) s_wbase[32] = incl;
    }
    __syncthreads();

    int b0 = s_wbase[warp] >> 16;
    int b1 = s_wbase[warp] & 0xffff;
    unsigned pre = (1u << lane) - 1u;
    #pragma unroll
    for (int k = 0; k < 4; k++) {
        if (rem0[k] >= 0)
            s_rec0[b0 + __popc(m0[k] & pre)] = make_uint2((unsigned)rem0[k], dep[k]);
        if (rem1[k] >= 0)
            s_rec1[b1 + __popc(m1[k] & pre)] = make_uint2((unsigned)rem1[k], dep[k]);
        b0 += __popc(m0[k]);
        b1 += __popc(m1[k]);
    }

    /* background rows for this block's two columns (127 rows x 2 cols) */
    if (tid < 254) {
        int r = tid >> 1;
        int row = (r < 64) ? r : r + 129;        /* 0..63 and 193..255 */
        out[row * IMG + c0 + (tid & 1)] = 1.0f;
    }
    __syncthreads();
    int nc0 = s_wbase[32] >> 16;
    int nc1 = s_wbase[32] & 0xffff;

    /* phase B: tid = [dyidx:6][colsel:1][oct:3]; dy = dyidx+1 in 1..64.
       Row symmetry: out[128+dy] == out[128-dy]. Row 128 = unconditional min. */
    int oct    = tid & 7;
    int colsel = (tid >> 3) & 1;
    int dy     = (tid >> 4) + 1;
    int d2     = dy * dy;
    const uint2* lst = colsel ? s_rec1 : s_rec0;
    int nc = colsel ? nc1 : nc0;

    float mv = 1.0f, mvu = 1.0f;
    #pragma unroll 4
    for (int e = oct; e < nc; e += 8) {
        uint2 rr = lst[e];
        float d = __uint_as_float(rr.y);
        mvu = fminf(mvu, d);                     /* row 128 (rem >= 0 always) */
        if (d2 <= (int)rr.x) mv = fminf(mv, d);
    }
    /* reduce over oct (lane bits 0..2) */
    #pragma unroll
    for (int off = 1; off < 8; off <<= 1) {
        mv  = fminf(mv,  __shfl_xor_sync(0xffffffffu, mv,  off));
        mvu = fminf(mvu, __shfl_xor_sync(0xffffffffu, mvu, off));
    }
    if (oct == 0) {
        int col = c0 + colsel;
        out[(128 + dy) * IMG + col] = mv;
        out[(128 - dy) * IMG + col] = mv;
        if (dy == 1) out[128 * IMG + col] = mvu;
    }
}

extern "C" void kernel_launch(void* const* d_in, const int* in_sizes, int n_in,
                              void* d_out, int out_size) {
    const float* agent  = (const float*)d_in[0];
    const float* goal   = (const float*)d_in[1];
    const float* others = (const float*)d_in[2];
    const float* obs    = (const float*)d_in[3];
    float* out          = (float*)d_out;

    render_kernel<<<NB, PT>>>(agent, goal, others, obs, out);
}